// round 7
// baseline (speedup 1.0000x reference)
#include <cuda_runtime.h>
#include <cstdint>

#define Bb   64
#define Tt   1024
#define Ee   512
#define Vv   256
#define CL   8          // cluster size = CTAs per batch-group

typedef unsigned long long u64;

// ---------------- device scratch ----------------
__device__ float g_P[Vv * Ee];                 // P[v][o] = emb[v]·w_x[o] + b_cell[o]
__device__ float g_hs[(size_t)Tt * Bb * Ee];   // hs[t][b][e]  (128 MB)

// ---------------- packed f32x2 helpers ----------------
__device__ __forceinline__ u64 fma2(u64 a, u64 b, u64 c) {
    u64 d;
    asm("fma.rn.f32x2 %0, %1, %2, %3;" : "=l"(d) : "l"(a), "l"(b), "l"(c));
    return d;
}
__device__ __forceinline__ float lo32(u64 v) { return __uint_as_float((unsigned)(v & 0xffffffffull)); }
__device__ __forceinline__ float hi32(u64 v) { return __uint_as_float((unsigned)(v >> 32)); }
__device__ __forceinline__ float hsum(u64 v) { return lo32(v) + hi32(v); }

__device__ __forceinline__ uint32_t smem_u32(const void* p) {
    uint32_t a;
    asm("{ .reg .u64 t; cvta.to.shared.u64 t, %1; cvt.u32.u64 %0, t; }" : "=r"(a) : "l"(p));
    return a;
}
__device__ __forceinline__ uint32_t mapa_sh(uint32_t local, uint32_t rank) {
    uint32_t r;
    asm("mapa.shared::cluster.u32 %0, %1, %2;" : "=r"(r) : "r"(local), "r"(rank));
    return r;
}
__device__ __forceinline__ uint32_t my_rank() {
    uint32_t r; asm("mov.u32 %0, %%cluster_ctarank;" : "=r"(r)); return r;
}
__device__ __forceinline__ void mbar_init(uint32_t a, unsigned cnt) {
    asm volatile("mbarrier.init.shared.b64 [%0], %1;" :: "r"(a), "r"(cnt) : "memory");
}
__device__ __forceinline__ void mbar_arrive_tx(uint32_t a, unsigned tx) {
    asm volatile("mbarrier.arrive.expect_tx.shared.b64 _, [%0], %1;" :: "r"(a), "r"(tx) : "memory");
}
__device__ __forceinline__ void mbar_wait(uint32_t mb, unsigned parity) {
    uint32_t done;
    asm volatile(
        "{\n\t.reg .pred q;\n\t"
        "mbarrier.try_wait.parity.acquire.cta.shared::cta.b64 q, [%1], %2;\n\t"
        "selp.b32 %0, 1, 0, q;\n\t}"
        : "=r"(done) : "r"(mb), "r"(parity) : "memory");
    if (!done) {
        asm volatile(
            "{\n\t.reg .pred Q;\n\t"
            "WL_%=:\n\t"
            "mbarrier.try_wait.parity.acquire.cta.shared::cta.b64 Q, [%0], %1, 0x989680;\n\t"
            "@Q bra.uni WD_%=;\n\t"
            "bra.uni WL_%=;\n\t"
            "WD_%=:\n\t}"
            :: "r"(mb), "r"(parity) : "memory");
    }
}

// ---------------- P = emb @ w_x^T + b_cell   (256 x 512, K=512) ----------------
__global__ void p_gemm_kernel(const float* __restrict__ emb,
                              const float* __restrict__ w_cell,
                              const float* __restrict__ b_cell) {
    __shared__ float As[64][16];
    __shared__ float Bs[16][64];
    int tid = threadIdx.x;
    int rbase = blockIdx.x * 64;   // v
    int cbase = blockIdx.y * 64;   // o
    int ti = tid >> 4, tj = tid & 15;
    int arow = tid >> 2, ac4 = (tid & 3) * 4;
    float acc[4][4] = {};

    for (int k0 = 0; k0 < Ee; k0 += 16) {
        float4 av = *(const float4*)&emb[(rbase + arow) * Ee + k0 + ac4];
        *(float4*)&As[arow][ac4] = av;
        float4 bv = *(const float4*)&w_cell[(size_t)(cbase + arow) * (2 * Ee) + k0 + ac4];
        Bs[ac4 + 0][arow] = bv.x; Bs[ac4 + 1][arow] = bv.y;
        Bs[ac4 + 2][arow] = bv.z; Bs[ac4 + 3][arow] = bv.w;
        __syncthreads();
#pragma unroll
        for (int kk = 0; kk < 16; kk++) {
            float a0 = As[ti * 4 + 0][kk];
            float a1 = As[ti * 4 + 1][kk];
            float a2 = As[ti * 4 + 2][kk];
            float a3 = As[ti * 4 + 3][kk];
            float4 b4 = *(const float4*)&Bs[kk][tj * 4];
            acc[0][0] = fmaf(a0, b4.x, acc[0][0]); acc[0][1] = fmaf(a0, b4.y, acc[0][1]);
            acc[0][2] = fmaf(a0, b4.z, acc[0][2]); acc[0][3] = fmaf(a0, b4.w, acc[0][3]);
            acc[1][0] = fmaf(a1, b4.x, acc[1][0]); acc[1][1] = fmaf(a1, b4.y, acc[1][1]);
            acc[1][2] = fmaf(a1, b4.z, acc[1][2]); acc[1][3] = fmaf(a1, b4.w, acc[1][3]);
            acc[2][0] = fmaf(a2, b4.x, acc[2][0]); acc[2][1] = fmaf(a2, b4.y, acc[2][1]);
            acc[2][2] = fmaf(a2, b4.z, acc[2][2]); acc[2][3] = fmaf(a2, b4.w, acc[2][3]);
            acc[3][0] = fmaf(a3, b4.x, acc[3][0]); acc[3][1] = fmaf(a3, b4.y, acc[3][1]);
            acc[3][2] = fmaf(a3, b4.z, acc[3][2]); acc[3][3] = fmaf(a3, b4.w, acc[3][3]);
        }
        __syncthreads();
    }
#pragma unroll
    for (int ii = 0; ii < 4; ii++) {
        int r = rbase + ti * 4 + ii;
        int c = cbase + tj * 4;
        float4 o;
        o.x = acc[ii][0] + b_cell[c + 0];
        o.y = acc[ii][1] + b_cell[c + 1];
        o.z = acc[ii][2] + b_cell[c + 2];
        o.w = acc[ii][3] + b_cell[c + 3];
        *(float4*)&g_P[r * Ee + c] = o;
    }
}

// ---------------- persistent recurrence kernel (cluster of 8, per-slice mbars) ----
// 128 CTAs = 16 clusters (batch-groups of 4) x 8 ranks (64-col tiles).
// h exchanged via per-warp 128B DSMEM bulk pushes; per-slice mbarriers;
// psum double-buffered by parity; ONE __syncthreads per step.
__global__ void __launch_bounds__(256, 1) __cluster_dims__(CL, 1, 1)
rnn_rec_kernel(const int* __restrict__ x,
               const float* __restrict__ w_cell,
               const float* __restrict__ h0) {
    __shared__ __align__(16) float hbuf[2][CL * 256];   // 2 x 8 KB  [p][slice][b][64]
    __shared__ __align__(16) float stag[2][256];        // 2 x 1 KB  [p][b*64+c]
    __shared__ float psum[2][4 * 8 * 64];               // 2 x 8 KB  [p][b][ks][c]
    __shared__ __align__(8) u64 mbar[2][CL];            // [p][slice]

    int tid = threadIdx.x;
    uint32_t rank = my_rank();           // 0..7 == col-tile io
    int io  = (int)rank;
    int grp = (int)(blockIdx.x >> 3);
    int obase = io * 64, bbase = grp * 4;
    int l  = tid & 31;       // lane
    int ks = tid >> 5;       // warp = k-slice (64 k); also producer-slice it waits on
    int k0 = ks * 64;

    uint32_t hbuf_a[2], stag_a[2], mbar_a[2];
    hbuf_a[0] = smem_u32(&hbuf[0][0]);  hbuf_a[1] = smem_u32(&hbuf[1][0]);
    stag_a[0] = smem_u32(&stag[0][0]);  stag_a[1] = smem_u32(&stag[1][0]);
    mbar_a[0] = smem_u32(&mbar[0][0]);  mbar_a[1] = smem_u32(&mbar[1][0]);

    // init + initial arming of all 16 mbarriers (before cluster sync)
    if (tid < CL) {
        mbar_init(mbar_a[0] + tid * 8, 1);
        mbar_init(mbar_a[1] + tid * 8, 1);
        mbar_arrive_tx(mbar_a[0] + tid * 8, 1024);
        mbar_arrive_tx(mbar_a[1] + tid * 8, 1024);
    }
    __syncthreads();
    asm volatile("barrier.cluster.arrive.aligned;" ::: "memory");

    // preload w_h for 2 cols: w_h[o][e] = w_cell[o*1024 + 512 + e]
    u64 wA[32], wB[32];
    {
        const u64* wp = (const u64*)w_cell;
        int baseA = ((obase + l)      * (2 * Ee) + Ee + k0) >> 1;
        int baseB = ((obase + l + 32) * (2 * Ee) + Ee + k0) >> 1;
#pragma unroll
        for (int j = 0; j < 32; j++) wA[j] = wp[baseA + j];
#pragma unroll
        for (int j = 0; j < 32; j++) wB[j] = wp[baseB + j];
    }

    // t=0 seed: hbuf[0][s][b][c] = h0[s*64 + c]
#pragma unroll
    for (int q = 0; q < 8; q++) {
        int idx = tid + q * 256;                  // 0..2047
        hbuf[0][idx] = h0[(idx >> 8) * 64 + (idx & 63)];
    }

    // reduce identity: warp w -> batch w>>1, cols (w&1)*32 + l
    int rb = tid >> 6, rc = tid & 63;
    const int* xrow = x + (bbase + rb) * Tt;
    const float* prow_base = g_P + obase + rc;

    // my 128B output chunk offset (bytes) inside a 1KB slice
    uint32_t chunk_off = (uint32_t)(ks * 128);
    uint32_t slice_off = (uint32_t)(io * 1024);

    asm volatile("barrier.cluster.wait.aligned;" ::: "memory");

    for (int t = 0; t < Tt; t++) {
        int p = t & 1;
        // ---- P-table prefetch (h-independent) ----
        int   xv = __ldg(xrow + t);
        float pv = __ldg(&prow_base[xv * Ee]);

        // ---- per-warp wait for slice ks of h_{t-1}, then re-arm ----
        if (t > 0) {
            unsigned parity = (unsigned)(((t - 1) >> 1) & 1);
            uint32_t mb = mbar_a[p] + (uint32_t)(ks * 8);
            mbar_wait(mb, parity);
            if (l == 0) mbar_arrive_tx(mb, 1024);
        }

        // ---- partial dots: 2 cols x 4 batches x 64 k per thread (local smem) ----
        const float* myhsm = &hbuf[p][ks * 256];
#pragma unroll
        for (int b = 0; b < 4; b++) {
            const ulonglong2* hp2 = (const ulonglong2*)(myhsm + b * 64);
            u64 aA0 = 0ull, aA1 = 0ull, aB0 = 0ull, aB1 = 0ull;
#pragma unroll
            for (int j = 0; j < 8; j++) {
                ulonglong2 h2a = hp2[2 * j];
                ulonglong2 h2b = hp2[2 * j + 1];
                aA0 = fma2(h2a.x, wA[4 * j + 0], aA0);
                aA1 = fma2(h2a.y, wA[4 * j + 1], aA1);
                aA0 = fma2(h2b.x, wA[4 * j + 2], aA0);
                aA1 = fma2(h2b.y, wA[4 * j + 3], aA1);
                aB0 = fma2(h2a.x, wB[4 * j + 0], aB0);
                aB1 = fma2(h2a.y, wB[4 * j + 1], aB1);
                aB0 = fma2(h2b.x, wB[4 * j + 2], aB0);
                aB1 = fma2(h2b.y, wB[4 * j + 3], aB1);
            }
            psum[p][(b * 8 + ks) * 64 + l]      = hsum(aA0) + hsum(aA1);
            psum[p][(b * 8 + ks) * 64 + l + 32] = hsum(aB0) + hsum(aB1);
        }
        __syncthreads();       // the ONLY CTA-wide barrier per step

        // ---- per-warp: reduce own chunk, tanh, publish ----
        float s = 0.f;
#pragma unroll
        for (int q = 0; q < 8; q++) s += psum[p][(rb * 8 + q) * 64 + rc];
        float val = tanhf(s + pv);

        // persist for head GEMM (off critical path)
        g_hs[((size_t)t * Bb + bbase + rb) * Ee + obase + rc] = val;

        if (t < Tt - 1) {
            int np = (t + 1) & 1;
            stag[np][tid] = val;                  // warp's 32 floats = 128B contiguous
            __syncwarp();
            if (l == 0) {
                asm volatile("fence.proxy.async.shared::cta;" ::: "memory");
                uint32_t src   = stag_a[np] + chunk_off;
                uint32_t dst_l = hbuf_a[np] + slice_off + chunk_off;
                uint32_t mb_l  = mbar_a[np] + (uint32_t)(io * 8);
#pragma unroll
                for (uint32_t r = 0; r < CL; r++) {
                    uint32_t dst = mapa_sh(dst_l, r);
                    uint32_t mb  = mapa_sh(mb_l, r);
                    asm volatile(
                        "cp.async.bulk.shared::cluster.shared::cta.mbarrier::complete_tx::bytes "
                        "[%0], [%1], %2, [%3];"
                        :: "r"(dst), "r"(src), "r"(128), "r"(mb) : "memory");
                }
            }
        }
    }

    // teardown: keep smem/mbars alive until the whole cluster is done
    asm volatile("barrier.cluster.arrive.aligned;" ::: "memory");
    asm volatile("barrier.cluster.wait.aligned;" ::: "memory");
}

// ---------------- head GEMM (R1 scalar, 64x64 tile) ----------------
__global__ void head_gemm_kernel(const float* __restrict__ w_head,
                                 const float* __restrict__ b_head,
                                 float* __restrict__ out) {
    __shared__ float As[64][16];   // [row][k]   rows r = t*B + b
    __shared__ float Bs[16][64];   // [k][col]
    int tid = threadIdx.x;
    int rbase = blockIdx.x * 64;
    int cbase = blockIdx.y * 64;
    int ti = tid >> 4, tj = tid & 15;
    int arow = tid >> 2, ac4 = (tid & 3) * 4;
    float acc[4][4] = {};

    for (int k0 = 0; k0 < Ee; k0 += 16) {
        float4 av = *(const float4*)&g_hs[(size_t)(rbase + arow) * Ee + k0 + ac4];
        *(float4*)&As[arow][ac4] = av;
        float4 bv = *(const float4*)&w_head[(size_t)(cbase + arow) * Ee + k0 + ac4];
        Bs[ac4 + 0][arow] = bv.x; Bs[ac4 + 1][arow] = bv.y;
        Bs[ac4 + 2][arow] = bv.z; Bs[ac4 + 3][arow] = bv.w;
        __syncthreads();
#pragma unroll
        for (int kk = 0; kk < 16; kk++) {
            float a0 = As[ti * 4 + 0][kk];
            float a1 = As[ti * 4 + 1][kk];
            float a2 = As[ti * 4 + 2][kk];
            float a3 = As[ti * 4 + 3][kk];
            float4 b4 = *(const float4*)&Bs[kk][tj * 4];
            acc[0][0] = fmaf(a0, b4.x, acc[0][0]); acc[0][1] = fmaf(a0, b4.y, acc[0][1]);
            acc[0][2] = fmaf(a0, b4.z, acc[0][2]); acc[0][3] = fmaf(a0, b4.w, acc[0][3]);
            acc[1][0] = fmaf(a1, b4.x, acc[1][0]); acc[1][1] = fmaf(a1, b4.y, acc[1][1]);
            acc[1][2] = fmaf(a1, b4.z, acc[1][2]); acc[1][3] = fmaf(a1, b4.w, acc[1][3]);
            acc[2][0] = fmaf(a2, b4.x, acc[2][0]); acc[2][1] = fmaf(a2, b4.y, acc[2][1]);
            acc[2][2] = fmaf(a2, b4.z, acc[2][2]); acc[2][3] = fmaf(a2, b4.w, acc[2][3]);
            acc[3][0] = fmaf(a3, b4.x, acc[3][0]); acc[3][1] = fmaf(a3, b4.y, acc[3][1]);
            acc[3][2] = fmaf(a3, b4.z, acc[3][2]); acc[3][3] = fmaf(a3, b4.w, acc[3][3]);
        }
        __syncthreads();
    }
#pragma unroll
    for (int ii = 0; ii < 4; ii++) {
        int r  = rbase + ti * 4 + ii;      // r = t*B + b
        int bb = r & (Bb - 1);
        int tt = r >> 6;
        int cc = cbase + tj * 4;
        float4 o;
        o.x = acc[ii][0] + b_head[cc + 0];
        o.y = acc[ii][1] + b_head[cc + 1];
        o.z = acc[ii][2] + b_head[cc + 2];
        o.w = acc[ii][3] + b_head[cc + 3];
        *(float4*)&out[(size_t)bb * (Tt * Vv) + (size_t)tt * Vv + cc] = o;
    }
}

// ---------------- launch ----------------
extern "C" void kernel_launch(void* const* d_in, const int* in_sizes, int n_in,
                              void* d_out, int out_size) {
    const int*   x      = (const int*)  d_in[0];
    const float* emb    = (const float*)d_in[1];
    const float* w_cell = (const float*)d_in[2];
    const float* b_cell = (const float*)d_in[3];
    const float* w_head = (const float*)d_in[4];
    const float* b_head = (const float*)d_in[5];
    const float* h0     = (const float*)d_in[6];
    float* out = (float*)d_out;

    p_gemm_kernel<<<dim3(Vv / 64, Ee / 64), 256>>>(emb, w_cell, b_cell);
    rnn_rec_kernel<<<128, 256>>>(x, w_cell, h0);
    head_gemm_kernel<<<dim3((Bb * Tt) / 64, Vv / 64), 256>>>(w_head, b_head, out);
}

// round 9
// speedup vs baseline: 1.1659x; 1.1659x over previous
#include <cuda_runtime.h>
#include <cstdint>

#define Bb   64
#define Tt   1024
#define Ee   512
#define Vv   256

typedef unsigned long long u64;

// ---------------- device scratch ----------------
__device__ float    g_P[Vv * Ee];                  // P[v][o] = emb[v]·w_x[o] + b_cell[o]
__device__ float    g_hs[(size_t)Tt * Bb * Ee];    // hs[t][b][e]  (128 MB)
__device__ unsigned g_flag[128 * 8 * 32];          // per-CTA per-warp-chunk flag, 128B stride

// ---------------- packed f32x2 helpers ----------------
__device__ __forceinline__ u64 fma2(u64 a, u64 b, u64 c) {
    u64 d;
    asm("fma.rn.f32x2 %0, %1, %2, %3;" : "=l"(d) : "l"(a), "l"(b), "l"(c));
    return d;
}
__device__ __forceinline__ float lo32(u64 v) { return __uint_as_float((unsigned)(v & 0xffffffffull)); }
__device__ __forceinline__ float hi32(u64 v) { return __uint_as_float((unsigned)(v >> 32)); }
__device__ __forceinline__ float hsum(u64 v) { return lo32(v) + hi32(v); }
__device__ __forceinline__ u64 pack2(float a) {
    u64 d; asm("mov.b64 %0, {%1, %1};" : "=l"(d) : "r"(__float_as_uint(a))); return d;
}
__device__ __forceinline__ void st_rel(unsigned* p, unsigned v) {
    asm volatile("st.release.gpu.global.u32 [%0], %1;" :: "l"(p), "r"(v) : "memory");
}
__device__ __forceinline__ unsigned ld_acq(const unsigned* p) {
    unsigned v;
    asm volatile("ld.acquire.gpu.global.u32 %0, [%1];" : "=r"(v) : "l"(p) : "memory");
    return v;
}

// ---------------- flag reset (each replay) ----------------
__global__ void zero_flag_kernel() {
    int i = blockIdx.x * 256 + threadIdx.x;
    g_flag[i] = 0u;
}

// ---------------- P = emb @ w_x^T + b_cell   (256 x 512, K=512) ----------------
__global__ void p_gemm_kernel(const float* __restrict__ emb,
                              const float* __restrict__ w_cell,
                              const float* __restrict__ b_cell) {
    __shared__ float As[64][16];
    __shared__ float Bs[16][64];
    int tid = threadIdx.x;
    int rbase = blockIdx.x * 64;   // v
    int cbase = blockIdx.y * 64;   // o
    int ti = tid >> 4, tj = tid & 15;
    int arow = tid >> 2, ac4 = (tid & 3) * 4;
    float acc[4][4] = {};

    for (int k0 = 0; k0 < Ee; k0 += 16) {
        float4 av = *(const float4*)&emb[(rbase + arow) * Ee + k0 + ac4];
        *(float4*)&As[arow][ac4] = av;
        float4 bv = *(const float4*)&w_cell[(size_t)(cbase + arow) * (2 * Ee) + k0 + ac4];
        Bs[ac4 + 0][arow] = bv.x; Bs[ac4 + 1][arow] = bv.y;
        Bs[ac4 + 2][arow] = bv.z; Bs[ac4 + 3][arow] = bv.w;
        __syncthreads();
#pragma unroll
        for (int kk = 0; kk < 16; kk++) {
            float a0 = As[ti * 4 + 0][kk];
            float a1 = As[ti * 4 + 1][kk];
            float a2 = As[ti * 4 + 2][kk];
            float a3 = As[ti * 4 + 3][kk];
            float4 b4 = *(const float4*)&Bs[kk][tj * 4];
            acc[0][0] = fmaf(a0, b4.x, acc[0][0]); acc[0][1] = fmaf(a0, b4.y, acc[0][1]);
            acc[0][2] = fmaf(a0, b4.z, acc[0][2]); acc[0][3] = fmaf(a0, b4.w, acc[0][3]);
            acc[1][0] = fmaf(a1, b4.x, acc[1][0]); acc[1][1] = fmaf(a1, b4.y, acc[1][1]);
            acc[1][2] = fmaf(a1, b4.z, acc[1][2]); acc[1][3] = fmaf(a1, b4.w, acc[1][3]);
            acc[2][0] = fmaf(a2, b4.x, acc[2][0]); acc[2][1] = fmaf(a2, b4.y, acc[2][1]);
            acc[2][2] = fmaf(a2, b4.z, acc[2][2]); acc[2][3] = fmaf(a2, b4.w, acc[2][3]);
            acc[3][0] = fmaf(a3, b4.x, acc[3][0]); acc[3][1] = fmaf(a3, b4.y, acc[3][1]);
            acc[3][2] = fmaf(a3, b4.z, acc[3][2]); acc[3][3] = fmaf(a3, b4.w, acc[3][3]);
        }
        __syncthreads();
    }
#pragma unroll
    for (int ii = 0; ii < 4; ii++) {
        int r = rbase + ti * 4 + ii;
        int c = cbase + tj * 4;
        float4 o;
        o.x = acc[ii][0] + b_cell[c + 0];
        o.y = acc[ii][1] + b_cell[c + 1];
        o.z = acc[ii][2] + b_cell[c + 2];
        o.w = acc[ii][3] + b_cell[c + 3];
        *(float4*)&g_P[r * Ee + c] = o;
    }
}

// ---------------- persistent recurrence kernel (R6, unchanged) ----------------
// 128 CTAs = 16 batch-groups (4 rows) x 8 col-tiles (64 cols).
// Exchange via L2 (g_hs STG doubles as publication) with per-warp-chunk flags.
// One __syncthreads per step; psum double-buffered by parity.
__global__ void __launch_bounds__(256, 1)
rnn_rec_kernel(const int* __restrict__ x,
               const float* __restrict__ w_cell,
               const float* __restrict__ h0) {
    __shared__ __align__(16) float hsm[8 * 256];     // 8 KB: per-warp 4b x 64k
    __shared__ float psum[2][4 * 8 * 64];            // 2 x 8 KB: [p][b][ks][c]

    int tid = threadIdx.x;
    int bid = blockIdx.x;
    int io  = bid & 7,  grp = bid >> 3;
    int obase = io * 64, bbase = grp * 4;
    int l  = tid & 31;       // lane
    int ks = tid >> 5;       // warp = k-slice (64 k) AND producer-chunk id
    int k0 = ks * 64;

    // preload w_h for 2 cols: w_h[o][e] = w_cell[o*1024 + 512 + e]
    u64 wA[32], wB[32];
    {
        const u64* wp = (const u64*)w_cell;
        int baseA = ((obase + l)      * (2 * Ee) + Ee + k0) >> 1;
        int baseB = ((obase + l + 32) * (2 * Ee) + Ee + k0) >> 1;
#pragma unroll
        for (int j = 0; j < 32; j++) wA[j] = wp[baseA + j];
#pragma unroll
        for (int j = 0; j < 32; j++) wB[j] = wp[baseB + j];
    }

    // producer side: this warp's chunk flag (batch ks>>1, col-half ks&1)
    unsigned* myflag = &g_flag[(bid * 8 + ks) * 32];

    // consumer side: producer CTA = grp*8 + ks; this thread's 2 loads touch
    // chunks c0 and c0+4 of that producer.
    int c0 = ((l >> 4) << 1) | ((l & 15) >> 3);     // bq*2 + half
    const unsigned* fA = &g_flag[((grp * 8 + ks) * 8 + c0) * 32];
    const unsigned* fB = fA + 4 * 32;

    // reduce identity: b = tid>>6, c = tid&63  (warp w => batch w>>1, cols (w&1)*32..)
    int rb = tid >> 6, rc = tid & 63;
    const int* xrow = x + (bbase + rb) * Tt;
    const float* prow_base = g_P + obase + rc;

    float* myhsm = hsm + ks * 256;

    for (int t = 0; t < Tt; t++) {
        int p = t & 1;
        // ---- P-table prefetch (h-independent) ----
        int   xv = __ldg(xrow + t);
        float pv = __ldg(&prow_base[xv * Ee]);

        // ---- gather this warp's k-slice (4 batches x 64 k) ----
        if (t == 0) {
#pragma unroll
            for (int q = 0; q < 2; q++) {
                int idx = l + 32 * q;
                int kk  = (idx & 15) * 4;
                *(float4*)&myhsm[(idx >> 4) * 64 + kk] = *(const float4*)&h0[k0 + kk];
            }
        } else {
            // poll the two producer chunks this thread reads (acquire orders the LDGs)
            unsigned a, b;
            do { a = ld_acq(fA); b = ld_acq(fB); } while (a < (unsigned)t || b < (unsigned)t);
#pragma unroll
            for (int q = 0; q < 2; q++) {
                int idx = l + 32 * q;
                int bq  = idx >> 4;
                int kk  = (idx & 15) * 4;
                const float4* src = (const float4*)(g_hs +
                    ((size_t)(t - 1) * Bb + bbase + bq) * Ee + k0 + kk);
                *(float4*)&myhsm[bq * 64 + kk] = __ldcg(src);
            }
        }
        __syncwarp();

        // ---- partial dots: 2 cols x 4 batches x 64 k per thread ----
#pragma unroll
        for (int b = 0; b < 4; b++) {
            const ulonglong2* hp2 = (const ulonglong2*)(myhsm + b * 64);
            u64 aA0 = 0ull, aA1 = 0ull, aB0 = 0ull, aB1 = 0ull;
#pragma unroll
            for (int j = 0; j < 8; j++) {
                ulonglong2 h2a = hp2[2 * j];
                ulonglong2 h2b = hp2[2 * j + 1];
                aA0 = fma2(h2a.x, wA[4 * j + 0], aA0);
                aA1 = fma2(h2a.y, wA[4 * j + 1], aA1);
                aA0 = fma2(h2b.x, wA[4 * j + 2], aA0);
                aA1 = fma2(h2b.y, wA[4 * j + 3], aA1);
                aB0 = fma2(h2a.x, wB[4 * j + 0], aB0);
                aB1 = fma2(h2a.y, wB[4 * j + 1], aB1);
                aB0 = fma2(h2b.x, wB[4 * j + 2], aB0);
                aB1 = fma2(h2b.y, wB[4 * j + 3], aB1);
            }
            psum[p][(b * 8 + ks) * 64 + l]      = hsum(aA0) + hsum(aA1);
            psum[p][(b * 8 + ks) * 64 + l + 32] = hsum(aB0) + hsum(aB1);
        }
        __syncthreads();       // the ONLY CTA-wide barrier per step

        // ---- per-warp: reduce own chunk, tanh, publish, release flag ----
        {
            float s = 0.f;
#pragma unroll
            for (int q = 0; q < 8; q++) s += psum[p][(rb * 8 + q) * 64 + rc];
            float val = tanhf(s + pv);
            g_hs[((size_t)t * Bb + bbase + rb) * Ee + obase + rc] = val;
            __syncwarp();
            if (l == 0 && t < Tt - 1) st_rel(myflag, (unsigned)(t + 1));
        }
    }
}

// ---------------- head GEMM: f32x2 with pre-packed A in shared, 64x64 tile ----------------
// out[b][t][v] = hs[t][b][:] · w_head[v][:] + b_head[v]
__global__ void __launch_bounds__(256)
head_gemm_kernel(const float* __restrict__ w_head,
                 const float* __restrict__ b_head,
                 float* __restrict__ out) {
    __shared__ __align__(16) u64   Asp[64][16];   // 8 KB    [row][k] packed {a,a}
    __shared__ __align__(16) float Bs[16][68];    // 4.25 KB [k][col], padded rows (16B-mult)
    int tid = threadIdx.x;
    int rbase = blockIdx.x * 64;
    int cbase = blockIdx.y * 64;
    int ti = tid >> 4, tj = tid & 15;
    int arow = tid >> 2, ac4 = (tid & 3) * 4;

    u64 acc[4][2];
#pragma unroll
    for (int i = 0; i < 4; i++) { acc[i][0] = 0ull; acc[i][1] = 0ull; }

    for (int k0 = 0; k0 < Ee; k0 += 16) {
        float4 av = *(const float4*)&g_hs[(size_t)(rbase + arow) * Ee + k0 + ac4];
        Asp[arow][ac4 + 0] = pack2(av.x);
        Asp[arow][ac4 + 1] = pack2(av.y);
        Asp[arow][ac4 + 2] = pack2(av.z);
        Asp[arow][ac4 + 3] = pack2(av.w);
        float4 bv = *(const float4*)&w_head[(size_t)(cbase + arow) * Ee + k0 + ac4];
        Bs[ac4 + 0][arow] = bv.x; Bs[ac4 + 1][arow] = bv.y;
        Bs[ac4 + 2][arow] = bv.z; Bs[ac4 + 3][arow] = bv.w;
        __syncthreads();
#pragma unroll
        for (int kk = 0; kk < 16; kk++) {
            u64 a0 = Asp[ti * 4 + 0][kk];
            u64 a1 = Asp[ti * 4 + 1][kk];
            u64 a2 = Asp[ti * 4 + 2][kk];
            u64 a3 = Asp[ti * 4 + 3][kk];
            ulonglong2 b2 = *(const ulonglong2*)&Bs[kk][tj * 4];
            acc[0][0] = fma2(a0, b2.x, acc[0][0]); acc[0][1] = fma2(a0, b2.y, acc[0][1]);
            acc[1][0] = fma2(a1, b2.x, acc[1][0]); acc[1][1] = fma2(a1, b2.y, acc[1][1]);
            acc[2][0] = fma2(a2, b2.x, acc[2][0]); acc[2][1] = fma2(a2, b2.y, acc[2][1]);
            acc[3][0] = fma2(a3, b2.x, acc[3][0]); acc[3][1] = fma2(a3, b2.y, acc[3][1]);
        }
        __syncthreads();
    }
#pragma unroll
    for (int ii = 0; ii < 4; ii++) {
        int r  = rbase + ti * 4 + ii;      // r = t*B + b
        int bb = r & (Bb - 1);
        int tt = r >> 6;
        int cc = cbase + tj * 4;
        float4 o;
        o.x = lo32(acc[ii][0]) + b_head[cc + 0];
        o.y = hi32(acc[ii][0]) + b_head[cc + 1];
        o.z = lo32(acc[ii][1]) + b_head[cc + 2];
        o.w = hi32(acc[ii][1]) + b_head[cc + 3];
        *(float4*)&out[(size_t)bb * (Tt * Vv) + (size_t)tt * Vv + cc] = o;
    }
}

// ---------------- launch ----------------
extern "C" void kernel_launch(void* const* d_in, const int* in_sizes, int n_in,
                              void* d_out, int out_size) {
    const int*   x      = (const int*)  d_in[0];
    const float* emb    = (const float*)d_in[1];
    const float* w_cell = (const float*)d_in[2];
    const float* b_cell = (const float*)d_in[3];
    const float* w_head = (const float*)d_in[4];
    const float* b_head = (const float*)d_in[5];
    const float* h0     = (const float*)d_in[6];
    float* out = (float*)d_out;

    zero_flag_kernel<<<128, 256>>>();
    p_gemm_kernel<<<dim3(Vv / 64, Ee / 64), 256>>>(emb, w_cell, b_cell);
    rnn_rec_kernel<<<128, 256>>>(x, w_cell, h0);
    head_gemm_kernel<<<dim3((Bb * Tt) / 64, Vv / 64), 256>>>(w_head, b_head, out);
}

// round 10
// speedup vs baseline: 1.1671x; 1.0010x over previous
#include <cuda_runtime.h>
#include <cstdint>

#define Bb   64
#define Tt   1024
#define Ee   512
#define Vv   256

typedef unsigned long long u64;

// ---------------- device scratch ----------------
__device__ float    g_P[Vv * Ee];                  // P[v][o] = emb[v]·w_x[o] + b_cell[o]
__device__ float    g_hs[(size_t)Tt * Bb * Ee];    // hs[t][b][e]  (128 MB)
__device__ unsigned g_flag[128 * 8 * 32];          // per-CTA per-warp-chunk flag, 128B stride

// ---------------- packed f32x2 helpers ----------------
__device__ __forceinline__ u64 fma2(u64 a, u64 b, u64 c) {
    u64 d;
    asm("fma.rn.f32x2 %0, %1, %2, %3;" : "=l"(d) : "l"(a), "l"(b), "l"(c));
    return d;
}
__device__ __forceinline__ float lo32(u64 v) { return __uint_as_float((unsigned)(v & 0xffffffffull)); }
__device__ __forceinline__ float hi32(u64 v) { return __uint_as_float((unsigned)(v >> 32)); }
__device__ __forceinline__ float hsum(u64 v) { return lo32(v) + hi32(v); }
__device__ __forceinline__ u64 pack2(float a) {
    u64 d; asm("mov.b64 %0, {%1, %1};" : "=l"(d) : "r"(__float_as_uint(a))); return d;
}
__device__ __forceinline__ void st_rel(unsigned* p, unsigned v) {
    asm volatile("st.release.gpu.global.u32 [%0], %1;" :: "l"(p), "r"(v) : "memory");
}
__device__ __forceinline__ unsigned ld_acq(const unsigned* p) {
    unsigned v;
    asm volatile("ld.acquire.gpu.global.u32 %0, [%1];" : "=r"(v) : "l"(p) : "memory");
    return v;
}

// ---------------- flag reset (each replay) ----------------
__global__ void zero_flag_kernel() {
    int i = blockIdx.x * 256 + threadIdx.x;
    g_flag[i] = 0u;
}

// ---------------- P = emb @ w_x^T + b_cell   (256 x 512, K=512) ----------------
__global__ void p_gemm_kernel(const float* __restrict__ emb,
                              const float* __restrict__ w_cell,
                              const float* __restrict__ b_cell) {
    __shared__ float As[64][16];
    __shared__ float Bs[16][64];
    int tid = threadIdx.x;
    int rbase = blockIdx.x * 64;   // v
    int cbase = blockIdx.y * 64;   // o
    int ti = tid >> 4, tj = tid & 15;
    int arow = tid >> 2, ac4 = (tid & 3) * 4;
    float acc[4][4] = {};

    for (int k0 = 0; k0 < Ee; k0 += 16) {
        float4 av = *(const float4*)&emb[(rbase + arow) * Ee + k0 + ac4];
        *(float4*)&As[arow][ac4] = av;
        float4 bv = *(const float4*)&w_cell[(size_t)(cbase + arow) * (2 * Ee) + k0 + ac4];
        Bs[ac4 + 0][arow] = bv.x; Bs[ac4 + 1][arow] = bv.y;
        Bs[ac4 + 2][arow] = bv.z; Bs[ac4 + 3][arow] = bv.w;
        __syncthreads();
#pragma unroll
        for (int kk = 0; kk < 16; kk++) {
            float a0 = As[ti * 4 + 0][kk];
            float a1 = As[ti * 4 + 1][kk];
            float a2 = As[ti * 4 + 2][kk];
            float a3 = As[ti * 4 + 3][kk];
            float4 b4 = *(const float4*)&Bs[kk][tj * 4];
            acc[0][0] = fmaf(a0, b4.x, acc[0][0]); acc[0][1] = fmaf(a0, b4.y, acc[0][1]);
            acc[0][2] = fmaf(a0, b4.z, acc[0][2]); acc[0][3] = fmaf(a0, b4.w, acc[0][3]);
            acc[1][0] = fmaf(a1, b4.x, acc[1][0]); acc[1][1] = fmaf(a1, b4.y, acc[1][1]);
            acc[1][2] = fmaf(a1, b4.z, acc[1][2]); acc[1][3] = fmaf(a1, b4.w, acc[1][3]);
            acc[2][0] = fmaf(a2, b4.x, acc[2][0]); acc[2][1] = fmaf(a2, b4.y, acc[2][1]);
            acc[2][2] = fmaf(a2, b4.z, acc[2][2]); acc[2][3] = fmaf(a2, b4.w, acc[2][3]);
            acc[3][0] = fmaf(a3, b4.x, acc[3][0]); acc[3][1] = fmaf(a3, b4.y, acc[3][1]);
            acc[3][2] = fmaf(a3, b4.z, acc[3][2]); acc[3][3] = fmaf(a3, b4.w, acc[3][3]);
        }
        __syncthreads();
    }
#pragma unroll
    for (int ii = 0; ii < 4; ii++) {
        int r = rbase + ti * 4 + ii;
        int c = cbase + tj * 4;
        float4 o;
        o.x = acc[ii][0] + b_cell[c + 0];
        o.y = acc[ii][1] + b_cell[c + 1];
        o.z = acc[ii][2] + b_cell[c + 2];
        o.w = acc[ii][3] + b_cell[c + 3];
        *(float4*)&g_P[r * Ee + c] = o;
    }
}

// ---------------- persistent recurrence kernel (R6, unchanged) ----------------
__global__ void __launch_bounds__(256, 1)
rnn_rec_kernel(const int* __restrict__ x,
               const float* __restrict__ w_cell,
               const float* __restrict__ h0) {
    __shared__ __align__(16) float hsm[8 * 256];     // 8 KB: per-warp 4b x 64k
    __shared__ float psum[2][4 * 8 * 64];            // 2 x 8 KB: [p][b][ks][c]

    int tid = threadIdx.x;
    int bid = blockIdx.x;
    int io  = bid & 7,  grp = bid >> 3;
    int obase = io * 64, bbase = grp * 4;
    int l  = tid & 31;       // lane
    int ks = tid >> 5;       // warp = k-slice (64 k) AND producer-chunk id
    int k0 = ks * 64;

    // preload w_h for 2 cols: w_h[o][e] = w_cell[o*1024 + 512 + e]
    u64 wA[32], wB[32];
    {
        const u64* wp = (const u64*)w_cell;
        int baseA = ((obase + l)      * (2 * Ee) + Ee + k0) >> 1;
        int baseB = ((obase + l + 32) * (2 * Ee) + Ee + k0) >> 1;
#pragma unroll
        for (int j = 0; j < 32; j++) wA[j] = wp[baseA + j];
#pragma unroll
        for (int j = 0; j < 32; j++) wB[j] = wp[baseB + j];
    }

    // producer side: this warp's chunk flag (batch ks>>1, col-half ks&1)
    unsigned* myflag = &g_flag[(bid * 8 + ks) * 32];

    // consumer side: producer CTA = grp*8 + ks; chunks c0 and c0+4
    int c0 = ((l >> 4) << 1) | ((l & 15) >> 3);     // bq*2 + half
    const unsigned* fA = &g_flag[((grp * 8 + ks) * 8 + c0) * 32];
    const unsigned* fB = fA + 4 * 32;

    // reduce identity: b = tid>>6, c = tid&63
    int rb = tid >> 6, rc = tid & 63;
    const int* xrow = x + (bbase + rb) * Tt;
    const float* prow_base = g_P + obase + rc;

    float* myhsm = hsm + ks * 256;

    for (int t = 0; t < Tt; t++) {
        int p = t & 1;
        // ---- P-table prefetch (h-independent) ----
        int   xv = __ldg(xrow + t);
        float pv = __ldg(&prow_base[xv * Ee]);

        // ---- gather this warp's k-slice (4 batches x 64 k) ----
        if (t == 0) {
#pragma unroll
            for (int q = 0; q < 2; q++) {
                int idx = l + 32 * q;
                int kk  = (idx & 15) * 4;
                *(float4*)&myhsm[(idx >> 4) * 64 + kk] = *(const float4*)&h0[k0 + kk];
            }
        } else {
            unsigned a, b;
            do { a = ld_acq(fA); b = ld_acq(fB); } while (a < (unsigned)t || b < (unsigned)t);
#pragma unroll
            for (int q = 0; q < 2; q++) {
                int idx = l + 32 * q;
                int bq  = idx >> 4;
                int kk  = (idx & 15) * 4;
                const float4* src = (const float4*)(g_hs +
                    ((size_t)(t - 1) * Bb + bbase + bq) * Ee + k0 + kk);
                *(float4*)&myhsm[bq * 64 + kk] = __ldcg(src);
            }
        }
        __syncwarp();

        // ---- partial dots: 2 cols x 4 batches x 64 k per thread ----
#pragma unroll
        for (int b = 0; b < 4; b++) {
            const ulonglong2* hp2 = (const ulonglong2*)(myhsm + b * 64);
            u64 aA0 = 0ull, aA1 = 0ull, aB0 = 0ull, aB1 = 0ull;
#pragma unroll
            for (int j = 0; j < 8; j++) {
                ulonglong2 h2a = hp2[2 * j];
                ulonglong2 h2b = hp2[2 * j + 1];
                aA0 = fma2(h2a.x, wA[4 * j + 0], aA0);
                aA1 = fma2(h2a.y, wA[4 * j + 1], aA1);
                aA0 = fma2(h2b.x, wA[4 * j + 2], aA0);
                aA1 = fma2(h2b.y, wA[4 * j + 3], aA1);
                aB0 = fma2(h2a.x, wB[4 * j + 0], aB0);
                aB1 = fma2(h2a.y, wB[4 * j + 1], aB1);
                aB0 = fma2(h2b.x, wB[4 * j + 2], aB0);
                aB1 = fma2(h2b.y, wB[4 * j + 3], aB1);
            }
            psum[p][(b * 8 + ks) * 64 + l]      = hsum(aA0) + hsum(aA1);
            psum[p][(b * 8 + ks) * 64 + l + 32] = hsum(aB0) + hsum(aB1);
        }
        __syncthreads();       // the ONLY CTA-wide barrier per step

        // ---- per-warp: reduce own chunk, tanh, publish, release flag ----
        {
            float s = 0.f;
#pragma unroll
            for (int q = 0; q < 8; q++) s += psum[p][(rb * 8 + q) * 64 + rc];
            float val = tanhf(s + pv);
            g_hs[((size_t)t * Bb + bbase + rb) * Ee + obase + rc] = val;
            __syncwarp();
            if (l == 0 && t < Tt - 1) st_rel(myflag, (unsigned)(t + 1));
        }
    }
}

// ---------------- head GEMM: f32x2, pre-packed A, paired-kk LDS.128 loads ----------------
// out[b][t][v] = hs[t][b][:] · w_head[v][:] + b_head[v]
__global__ void __launch_bounds__(256)
head_gemm_kernel(const float* __restrict__ w_head,
                 const float* __restrict__ b_head,
                 float* __restrict__ out) {
    __shared__ __align__(16) u64   Asp[64][16];   // 8 KB    [row][k] packed {a,a}
    __shared__ __align__(16) float Bs[16][68];    // 4.25 KB [k][col], padded rows (16B-mult)
    int tid = threadIdx.x;
    int rbase = blockIdx.x * 64;
    int cbase = blockIdx.y * 64;
    int ti = tid >> 4, tj = tid & 15;
    int arow = tid >> 2, ac4 = (tid & 3) * 4;

    u64 acc[4][2];
#pragma unroll
    for (int i = 0; i < 4; i++) { acc[i][0] = 0ull; acc[i][1] = 0ull; }

    for (int k0 = 0; k0 < Ee; k0 += 16) {
        float4 av = *(const float4*)&g_hs[(size_t)(rbase + arow) * Ee + k0 + ac4];
        Asp[arow][ac4 + 0] = pack2(av.x);
        Asp[arow][ac4 + 1] = pack2(av.y);
        Asp[arow][ac4 + 2] = pack2(av.z);
        Asp[arow][ac4 + 3] = pack2(av.w);
        float4 bv = *(const float4*)&w_head[(size_t)(cbase + arow) * Ee + k0 + ac4];
        Bs[ac4 + 0][arow] = bv.x; Bs[ac4 + 1][arow] = bv.y;
        Bs[ac4 + 2][arow] = bv.z; Bs[ac4 + 3][arow] = bv.w;
        __syncthreads();
#pragma unroll
        for (int kk = 0; kk < 16; kk += 2) {
            // one LDS.128 per A row covers kk and kk+1 (Asp rows are 128B-aligned)
            ulonglong2 a0 = *(const ulonglong2*)&Asp[ti * 4 + 0][kk];
            ulonglong2 a1 = *(const ulonglong2*)&Asp[ti * 4 + 1][kk];
            ulonglong2 a2 = *(const ulonglong2*)&Asp[ti * 4 + 2][kk];
            ulonglong2 a3 = *(const ulonglong2*)&Asp[ti * 4 + 3][kk];
            ulonglong2 bA = *(const ulonglong2*)&Bs[kk + 0][tj * 4];
            ulonglong2 bB = *(const ulonglong2*)&Bs[kk + 1][tj * 4];
            acc[0][0] = fma2(a0.x, bA.x, acc[0][0]); acc[0][1] = fma2(a0.x, bA.y, acc[0][1]);
            acc[1][0] = fma2(a1.x, bA.x, acc[1][0]); acc[1][1] = fma2(a1.x, bA.y, acc[1][1]);
            acc[2][0] = fma2(a2.x, bA.x, acc[2][0]); acc[2][1] = fma2(a2.x, bA.y, acc[2][1]);
            acc[3][0] = fma2(a3.x, bA.x, acc[3][0]); acc[3][1] = fma2(a3.x, bA.y, acc[3][1]);
            acc[0][0] = fma2(a0.y, bB.x, acc[0][0]); acc[0][1] = fma2(a0.y, bB.y, acc[0][1]);
            acc[1][0] = fma2(a1.y, bB.x, acc[1][0]); acc[1][1] = fma2(a1.y, bB.y, acc[1][1]);
            acc[2][0] = fma2(a2.y, bB.x, acc[2][0]); acc[2][1] = fma2(a2.y, bB.y, acc[2][1]);
            acc[3][0] = fma2(a3.y, bB.x, acc[3][0]); acc[3][1] = fma2(a3.y, bB.y, acc[3][1]);
        }
        __syncthreads();
    }
#pragma unroll
    for (int ii = 0; ii < 4; ii++) {
        int r  = rbase + ti * 4 + ii;      // r = t*B + b
        int bb = r & (Bb - 1);
        int tt = r >> 6;
        int cc = cbase + tj * 4;
        float4 o;
        o.x = lo32(acc[ii][0]) + b_head[cc + 0];
        o.y = hi32(acc[ii][0]) + b_head[cc + 1];
        o.z = lo32(acc[ii][1]) + b_head[cc + 2];
        o.w = hi32(acc[ii][1]) + b_head[cc + 3];
        *(float4*)&out[(size_t)bb * (Tt * Vv) + (size_t)tt * Vv + cc] = o;
    }
}

// ---------------- launch ----------------
extern "C" void kernel_launch(void* const* d_in, const int* in_sizes, int n_in,
                              void* d_out, int out_size) {
    const int*   x      = (const int*)  d_in[0];
    const float* emb    = (const float*)d_in[1];
    const float* w_cell = (const float*)d_in[2];
    const float* b_cell = (const float*)d_in[3];
    const float* w_head = (const float*)d_in[4];
    const float* b_head = (const float*)d_in[5];
    const float* h0     = (const float*)d_in[6];
    float* out = (float*)d_out;

    zero_flag_kernel<<<128, 256>>>();
    p_gemm_kernel<<<dim3(Vv / 64, Ee / 64), 256>>>(emb, w_cell, b_cell);
    rnn_rec_kernel<<<128, 256>>>(x, w_cell, h0);
    head_gemm_kernel<<<dim3((Bb * Tt) / 64, Vv / 64), 256>>>(w_head, b_head, out);
}

// round 12
// speedup vs baseline: 1.2703x; 1.0884x over previous
#include <cuda_runtime.h>
#include <cstdint>

#define Bb   64
#define Tt   1024
#define Ee   512
#define Vv   256

typedef unsigned long long u64;

// ---------------- device scratch ----------------
__device__ float    g_P[Vv * Ee];                  // P[v][o] = emb[v]·w_x[o] + b_cell[o]
__device__ float    g_hs[(size_t)Tt * Bb * Ee];    // hs[t][b][e]  (128 MB)
__device__ unsigned g_flag[128 * 8 * 32];          // per-CTA per-chunk flag, 128B stride
                                                   // chunk w = cols [w*8,w*8+8) x all 4 batches

// ---------------- packed f32x2 helpers ----------------
__device__ __forceinline__ u64 fma2(u64 a, u64 b, u64 c) {
    u64 d;
    asm("fma.rn.f32x2 %0, %1, %2, %3;" : "=l"(d) : "l"(a), "l"(b), "l"(c));
    return d;
}
__device__ __forceinline__ float lo32(u64 v) { return __uint_as_float((unsigned)(v & 0xffffffffull)); }
__device__ __forceinline__ float hi32(u64 v) { return __uint_as_float((unsigned)(v >> 32)); }
__device__ __forceinline__ float hsum(u64 v) { return lo32(v) + hi32(v); }
__device__ __forceinline__ void st_rel(unsigned* p, unsigned v) {
    asm volatile("st.release.gpu.global.u32 [%0], %1;" :: "l"(p), "r"(v) : "memory");
}
__device__ __forceinline__ unsigned ld_acq(const unsigned* p) {
    unsigned v;
    asm volatile("ld.acquire.gpu.global.u32 %0, [%1];" : "=r"(v) : "l"(p) : "memory");
    return v;
}

// ---------------- flag reset (each replay) ----------------
__global__ void zero_flag_kernel() {
    int i = blockIdx.x * 256 + threadIdx.x;
    g_flag[i] = 0u;
}

// ---------------- P = emb @ w_x^T + b_cell   (256 x 512, K=512) ----------------
__global__ void p_gemm_kernel(const float* __restrict__ emb,
                              const float* __restrict__ w_cell,
                              const float* __restrict__ b_cell) {
    __shared__ float As[64][16];
    __shared__ float Bs[16][64];
    int tid = threadIdx.x;
    int rbase = blockIdx.x * 64;   // v
    int cbase = blockIdx.y * 64;   // o
    int ti = tid >> 4, tj = tid & 15;
    int arow = tid >> 2, ac4 = (tid & 3) * 4;
    float acc[4][4] = {};

    for (int k0 = 0; k0 < Ee; k0 += 16) {
        float4 av = *(const float4*)&emb[(rbase + arow) * Ee + k0 + ac4];
        *(float4*)&As[arow][ac4] = av;
        float4 bv = *(const float4*)&w_cell[(size_t)(cbase + arow) * (2 * Ee) + k0 + ac4];
        Bs[ac4 + 0][arow] = bv.x; Bs[ac4 + 1][arow] = bv.y;
        Bs[ac4 + 2][arow] = bv.z; Bs[ac4 + 3][arow] = bv.w;
        __syncthreads();
#pragma unroll
        for (int kk = 0; kk < 16; kk++) {
            float a0 = As[ti * 4 + 0][kk];
            float a1 = As[ti * 4 + 1][kk];
            float a2 = As[ti * 4 + 2][kk];
            float a3 = As[ti * 4 + 3][kk];
            float4 b4 = *(const float4*)&Bs[kk][tj * 4];
            acc[0][0] = fmaf(a0, b4.x, acc[0][0]); acc[0][1] = fmaf(a0, b4.y, acc[0][1]);
            acc[0][2] = fmaf(a0, b4.z, acc[0][2]); acc[0][3] = fmaf(a0, b4.w, acc[0][3]);
            acc[1][0] = fmaf(a1, b4.x, acc[1][0]); acc[1][1] = fmaf(a1, b4.y, acc[1][1]);
            acc[1][2] = fmaf(a1, b4.z, acc[1][2]); acc[1][3] = fmaf(a1, b4.w, acc[1][3]);
            acc[2][0] = fmaf(a2, b4.x, acc[2][0]); acc[2][1] = fmaf(a2, b4.y, acc[2][1]);
            acc[2][2] = fmaf(a2, b4.z, acc[2][2]); acc[2][3] = fmaf(a2, b4.w, acc[2][3]);
            acc[3][0] = fmaf(a3, b4.x, acc[3][0]); acc[3][1] = fmaf(a3, b4.y, acc[3][1]);
            acc[3][2] = fmaf(a3, b4.z, acc[3][2]); acc[3][3] = fmaf(a3, b4.w, acc[3][3]);
        }
        __syncthreads();
    }
#pragma unroll
    for (int ii = 0; ii < 4; ii++) {
        int r = rbase + ti * 4 + ii;
        int c = cbase + tj * 4;
        float4 o;
        o.x = acc[ii][0] + b_cell[c + 0];
        o.y = acc[ii][1] + b_cell[c + 1];
        o.z = acc[ii][2] + b_cell[c + 2];
        o.w = acc[ii][3] + b_cell[c + 3];
        *(float4*)&g_P[r * Ee + c] = o;
    }
}

// ---------------- persistent recurrence kernel ----------------
// 128 CTAs = 16 batch-groups (4 rows) x 8 col-tiles (64 cols).
// Producer chunk = warp w -> cols [w*8,w*8+8) x ALL 4 batches => every consumer
// thread's two h-float4s (same 4-col window, two batches) covered by ONE flag.
// psum layout q*288 + b*72 + c : per-q stride 288 >= 4*72 (no overlap);
// 288 % 32 == 0 and 72 % 32 == 8 keep both write and read conflict-free.
__global__ void __launch_bounds__(256, 1)
rnn_rec_kernel(const int* __restrict__ x,
               const float* __restrict__ w_cell,
               const float* __restrict__ h0) {
    __shared__ __align__(16) float hsm[8 * 256];     // 8 KB: per-warp 4b x 64k
    __shared__ float psum[2][8 * 288];               // 2 x 9 KB: [p][q*288 + b*72 + c]

    int tid = threadIdx.x;
    int bid = blockIdx.x;
    int io  = bid & 7,  grp = bid >> 3;
    int obase = io * 64, bbase = grp * 4;
    int l  = tid & 31;       // lane
    int ks = tid >> 5;       // warp = k-slice (compute) AND chunk id (reduce)
    int k0 = ks * 64;

    // preload w_h for 2 cols: w_h[o][e] = w_cell[o*1024 + 512 + e]
    u64 wA[32], wB[32];
    {
        const u64* wp = (const u64*)w_cell;
        int baseA = ((obase + l)      * (2 * Ee) + Ee + k0) >> 1;
        int baseB = ((obase + l + 32) * (2 * Ee) + Ee + k0) >> 1;
#pragma unroll
        for (int j = 0; j < 32; j++) wA[j] = wp[baseA + j];
#pragma unroll
        for (int j = 0; j < 32; j++) wB[j] = wp[baseB + j];
    }

    // producer side: this warp's chunk flag (cols [ks*8, ks*8+8) x all batches)
    unsigned* myflag = &g_flag[(bid * 8 + ks) * 32];

    // consumer side: producer CTA = grp*8 + ks; this thread's 2 loads share one
    // 4-col window kk = (l&15)*4 -> chunk (l&15)>>1 covers both batches.
    const unsigned* fA = &g_flag[((grp * 8 + ks) * 8 + ((l & 15) >> 1)) * 32];

    // reduce identity: warp ks covers cols ks*8..ks*8+7; lane l -> b = l>>3, c = ks*8 + (l&7)
    int rb = l >> 3, rc = ks * 8 + (l & 7);
    const int* xrow = x + (bbase + rb) * Tt;
    const float* prow_base = g_P + obase + rc;

    // gather coordinates
    int bq0 = l >> 4, bq1 = (l + 32) >> 4;          // {0,1} and {2,3}
    int kk  = (l & 15) * 4;

    float* myhsm = hsm + ks * 256;

    for (int t = 0; t < Tt; t++) {
        int p = t & 1;
        // ---- P-table prefetch (h-independent) ----
        int   xv = __ldg(xrow + t);
        float pv = __ldg(&prow_base[xv * Ee]);

        // ---- gather this warp's k-slice (4 batches x 64 k) ----
        if (t == 0) {
#pragma unroll
            for (int q = 0; q < 2; q++) {
                int idx = l + 32 * q;
                int kq  = (idx & 15) * 4;
                *(float4*)&myhsm[(idx >> 4) * 64 + kq] = *(const float4*)&h0[k0 + kq];
            }
        } else {
            // single flag poll (acquire orders the subsequent LDGs)
            while (ld_acq(fA) < (unsigned)t) { }
            const float* base = g_hs + ((size_t)(t - 1) * Bb + bbase) * Ee + k0 + kk;
            float4 v0 = __ldcg((const float4*)(base + (size_t)bq0 * Ee));
            float4 v1 = __ldcg((const float4*)(base + (size_t)bq1 * Ee));
            *(float4*)&myhsm[bq0 * 64 + kk] = v0;
            *(float4*)&myhsm[bq1 * 64 + kk] = v1;
        }
        __syncwarp();

        // ---- partial dots: 2 cols x 4 batches x 64 k per thread ----
#pragma unroll
        for (int b = 0; b < 4; b++) {
            const ulonglong2* hp2 = (const ulonglong2*)(myhsm + b * 64);
            u64 aA0 = 0ull, aA1 = 0ull, aB0 = 0ull, aB1 = 0ull;
#pragma unroll
            for (int j = 0; j < 8; j++) {
                ulonglong2 h2a = hp2[2 * j];
                ulonglong2 h2b = hp2[2 * j + 1];
                aA0 = fma2(h2a.x, wA[4 * j + 0], aA0);
                aA1 = fma2(h2a.y, wA[4 * j + 1], aA1);
                aA0 = fma2(h2b.x, wA[4 * j + 2], aA0);
                aA1 = fma2(h2b.y, wA[4 * j + 3], aA1);
                aB0 = fma2(h2a.x, wB[4 * j + 0], aB0);
                aB1 = fma2(h2a.y, wB[4 * j + 1], aB1);
                aB0 = fma2(h2b.x, wB[4 * j + 2], aB0);
                aB1 = fma2(h2b.y, wB[4 * j + 3], aB1);
            }
            psum[p][ks * 288 + b * 72 + l]      = hsum(aA0) + hsum(aA1);
            psum[p][ks * 288 + b * 72 + l + 32] = hsum(aB0) + hsum(aB1);
        }
        __syncthreads();       // the ONLY CTA-wide barrier per step

        // ---- per-warp: reduce own chunk (8 cols x 4 batches), tanh, publish ----
        {
            float s = 0.f;
#pragma unroll
            for (int q = 0; q < 8; q++) s += psum[p][q * 288 + rb * 72 + rc];
            float val = tanhf(s + pv);
            g_hs[((size_t)t * Bb + bbase + rb) * Ee + obase + rc] = val;
            __syncwarp();
            if (l == 0 && t < Tt - 1) st_rel(myflag, (unsigned)(t + 1));
        }
    }
}

// ---------------- head GEMM (R1 scalar, 64x64 tile — proven 487us) ----------------
__global__ void head_gemm_kernel(const float* __restrict__ w_head,
                                 const float* __restrict__ b_head,
                                 float* __restrict__ out) {
    __shared__ float As[64][16];   // [row][k]   rows r = t*B + b
    __shared__ float Bs[16][64];   // [k][col]
    int tid = threadIdx.x;
    int rbase = blockIdx.x * 64;
    int cbase = blockIdx.y * 64;
    int ti = tid >> 4, tj = tid & 15;
    int arow = tid >> 2, ac4 = (tid & 3) * 4;
    float acc[4][4] = {};

    for (int k0 = 0; k0 < Ee; k0 += 16) {
        float4 av = *(const float4*)&g_hs[(size_t)(rbase + arow) * Ee + k0 + ac4];
        *(float4*)&As[arow][ac4] = av;
        float4 bv = *(const float4*)&w_head[(size_t)(cbase + arow) * Ee + k0 + ac4];
        Bs[ac4 + 0][arow] = bv.x; Bs[ac4 + 1][arow] = bv.y;
        Bs[ac4 + 2][arow] = bv.z; Bs[ac4 + 3][arow] = bv.w;
        __syncthreads();
#pragma unroll
        for (int kk = 0; kk < 16; kk++) {
            float a0 = As[ti * 4 + 0][kk];
            float a1 = As[ti * 4 + 1][kk];
            float a2 = As[ti * 4 + 2][kk];
            float a3 = As[ti * 4 + 3][kk];
            float4 b4 = *(const float4*)&Bs[kk][tj * 4];
            acc[0][0] = fmaf(a0, b4.x, acc[0][0]); acc[0][1] = fmaf(a0, b4.y, acc[0][1]);
            acc[0][2] = fmaf(a0, b4.z, acc[0][2]); acc[0][3] = fmaf(a0, b4.w, acc[0][3]);
            acc[1][0] = fmaf(a1, b4.x, acc[1][0]); acc[1][1] = fmaf(a1, b4.y, acc[1][1]);
            acc[1][2] = fmaf(a1, b4.z, acc[1][2]); acc[1][3] = fmaf(a1, b4.w, acc[1][3]);
            acc[2][0] = fmaf(a2, b4.x, acc[2][0]); acc[2][1] = fmaf(a2, b4.y, acc[2][1]);
            acc[2][2] = fmaf(a2, b4.z, acc[2][2]); acc[2][3] = fmaf(a2, b4.w, acc[2][3]);
            acc[3][0] = fmaf(a3, b4.x, acc[3][0]); acc[3][1] = fmaf(a3, b4.y, acc[3][1]);
            acc[3][2] = fmaf(a3, b4.z, acc[3][2]); acc[3][3] = fmaf(a3, b4.w, acc[3][3]);
        }
        __syncthreads();
    }
#pragma unroll
    for (int ii = 0; ii < 4; ii++) {
        int r  = rbase + ti * 4 + ii;      // r = t*B + b
        int bb = r & (Bb - 1);
        int tt = r >> 6;
        int cc = cbase + tj * 4;
        float4 o;
        o.x = acc[ii][0] + b_head[cc + 0];
        o.y = acc[ii][1] + b_head[cc + 1];
        o.z = acc[ii][2] + b_head[cc + 2];
        o.w = acc[ii][3] + b_head[cc + 3];
        *(float4*)&out[(size_t)bb * (Tt * Vv) + (size_t)tt * Vv + cc] = o;
    }
}

// ---------------- launch ----------------
extern "C" void kernel_launch(void* const* d_in, const int* in_sizes, int n_in,
                              void* d_out, int out_size) {
    const int*   x      = (const int*)  d_in[0];
    const float* emb    = (const float*)d_in[1];
    const float* w_cell = (const float*)d_in[2];
    const float* b_cell = (const float*)d_in[3];
    const float* w_head = (const float*)d_in[4];
    const float* b_head = (const float*)d_in[5];
    const float* h0     = (const float*)d_in[6];
    float* out = (float*)d_out;

    zero_flag_kernel<<<128, 256>>>();
    p_gemm_kernel<<<dim3(Vv / 64, Ee / 64), 256>>>(emb, w_cell, b_cell);
    rnn_rec_kernel<<<128, 256>>>(x, w_cell, h0);
    head_gemm_kernel<<<dim3((Bb * Tt) / 64, Vv / 64), 256>>>(w_head, b_head, out);
}

// round 13
// speedup vs baseline: 1.3054x; 1.0276x over previous
#include <cuda_runtime.h>
#include <cstdint>

#define Bb   64
#define Tt   1024
#define Ee   512
#define Vv   256

typedef unsigned long long u64;

// ---------------- device scratch ----------------
__device__ float    g_P[Vv * Ee];                  // P[v][o] = emb[v]·w_x[o] + b_cell[o]
__device__ float    g_hs[(size_t)Tt * Bb * Ee];    // hs[t][b][e]  (128 MB)
__device__ unsigned g_flag[128 * 8 * 32];          // per-CTA per-chunk flag, 128B stride

// ---------------- packed f32x2 helpers ----------------
__device__ __forceinline__ u64 fma2(u64 a, u64 b, u64 c) {
    u64 d;
    asm("fma.rn.f32x2 %0, %1, %2, %3;" : "=l"(d) : "l"(a), "l"(b), "l"(c));
    return d;
}
__device__ __forceinline__ float lo32(u64 v) { return __uint_as_float((unsigned)(v & 0xffffffffull)); }
__device__ __forceinline__ float hi32(u64 v) { return __uint_as_float((unsigned)(v >> 32)); }
__device__ __forceinline__ float hsum(u64 v) { return lo32(v) + hi32(v); }
__device__ __forceinline__ void st_rel(unsigned* p, unsigned v) {
    asm volatile("st.release.gpu.global.u32 [%0], %1;" :: "l"(p), "r"(v) : "memory");
}
__device__ __forceinline__ unsigned ld_acq(const unsigned* p) {
    unsigned v;
    asm volatile("ld.acquire.gpu.global.u32 %0, [%1];" : "=r"(v) : "l"(p) : "memory");
    return v;
}

// ---------------- flag reset (each replay) ----------------
__global__ void zero_flag_kernel() {
    int i = blockIdx.x * 256 + threadIdx.x;
    g_flag[i] = 0u;
}

// ---------------- P = emb @ w_x^T + b_cell   (256 x 512, K=512) ----------------
__global__ void p_gemm_kernel(const float* __restrict__ emb,
                              const float* __restrict__ w_cell,
                              const float* __restrict__ b_cell) {
    __shared__ float As[64][16];
    __shared__ float Bs[16][64];
    int tid = threadIdx.x;
    int rbase = blockIdx.x * 64;   // v
    int cbase = blockIdx.y * 64;   // o
    int ti = tid >> 4, tj = tid & 15;
    int arow = tid >> 2, ac4 = (tid & 3) * 4;
    float acc[4][4] = {};

    for (int k0 = 0; k0 < Ee; k0 += 16) {
        float4 av = *(const float4*)&emb[(rbase + arow) * Ee + k0 + ac4];
        *(float4*)&As[arow][ac4] = av;
        float4 bv = *(const float4*)&w_cell[(size_t)(cbase + arow) * (2 * Ee) + k0 + ac4];
        Bs[ac4 + 0][arow] = bv.x; Bs[ac4 + 1][arow] = bv.y;
        Bs[ac4 + 2][arow] = bv.z; Bs[ac4 + 3][arow] = bv.w;
        __syncthreads();
#pragma unroll
        for (int kk = 0; kk < 16; kk++) {
            float a0 = As[ti * 4 + 0][kk];
            float a1 = As[ti * 4 + 1][kk];
            float a2 = As[ti * 4 + 2][kk];
            float a3 = As[ti * 4 + 3][kk];
            float4 b4 = *(const float4*)&Bs[kk][tj * 4];
            acc[0][0] = fmaf(a0, b4.x, acc[0][0]); acc[0][1] = fmaf(a0, b4.y, acc[0][1]);
            acc[0][2] = fmaf(a0, b4.z, acc[0][2]); acc[0][3] = fmaf(a0, b4.w, acc[0][3]);
            acc[1][0] = fmaf(a1, b4.x, acc[1][0]); acc[1][1] = fmaf(a1, b4.y, acc[1][1]);
            acc[1][2] = fmaf(a1, b4.z, acc[1][2]); acc[1][3] = fmaf(a1, b4.w, acc[1][3]);
            acc[2][0] = fmaf(a2, b4.x, acc[2][0]); acc[2][1] = fmaf(a2, b4.y, acc[2][1]);
            acc[2][2] = fmaf(a2, b4.z, acc[2][2]); acc[2][3] = fmaf(a2, b4.w, acc[2][3]);
            acc[3][0] = fmaf(a3, b4.x, acc[3][0]); acc[3][1] = fmaf(a3, b4.y, acc[3][1]);
            acc[3][2] = fmaf(a3, b4.z, acc[3][2]); acc[3][3] = fmaf(a3, b4.w, acc[3][3]);
        }
        __syncthreads();
    }
#pragma unroll
    for (int ii = 0; ii < 4; ii++) {
        int r = rbase + ti * 4 + ii;
        int c = cbase + tj * 4;
        float4 o;
        o.x = acc[ii][0] + b_cell[c + 0];
        o.y = acc[ii][1] + b_cell[c + 1];
        o.z = acc[ii][2] + b_cell[c + 2];
        o.w = acc[ii][3] + b_cell[c + 3];
        *(float4*)&g_P[r * Ee + c] = o;
    }
}

// ---------------- persistent recurrence kernel (R12 + LDS pipelining) ----------------
__global__ void __launch_bounds__(256, 1)
rnn_rec_kernel(const int* __restrict__ x,
               const float* __restrict__ w_cell,
               const float* __restrict__ h0) {
    __shared__ __align__(16) float hsm[8 * 256];     // 8 KB
    __shared__ float psum[2][8 * 288];               // 2 x 9 KB: [p][q*288 + b*72 + c]

    int tid = threadIdx.x;
    int bid = blockIdx.x;
    int io  = bid & 7,  grp = bid >> 3;
    int obase = io * 64, bbase = grp * 4;
    int l  = tid & 31;
    int ks = tid >> 5;
    int k0 = ks * 64;

    // preload w_h for 2 cols
    u64 wA[32], wB[32];
    {
        const u64* wp = (const u64*)w_cell;
        int baseA = ((obase + l)      * (2 * Ee) + Ee + k0) >> 1;
        int baseB = ((obase + l + 32) * (2 * Ee) + Ee + k0) >> 1;
#pragma unroll
        for (int j = 0; j < 32; j++) wA[j] = wp[baseA + j];
#pragma unroll
        for (int j = 0; j < 32; j++) wB[j] = wp[baseB + j];
    }

    unsigned* myflag = &g_flag[(bid * 8 + ks) * 32];
    const unsigned* fA = &g_flag[((grp * 8 + ks) * 8 + ((l & 15) >> 1)) * 32];

    int rb = l >> 3, rc = ks * 8 + (l & 7);
    const int* xrow = x + (bbase + rb) * Tt;
    const float* prow_base = g_P + obase + rc;

    int bq0 = l >> 4, bq1 = (l + 32) >> 4;
    int kk  = (l & 15) * 4;

    float* myhsm = hsm + ks * 256;

    for (int t = 0; t < Tt; t++) {
        int p = t & 1;
        int   xv = __ldg(xrow + t);
        float pv = __ldg(&prow_base[xv * Ee]);

        if (t == 0) {
#pragma unroll
            for (int q = 0; q < 2; q++) {
                int idx = l + 32 * q;
                int kq  = (idx & 15) * 4;
                *(float4*)&myhsm[(idx >> 4) * 64 + kq] = *(const float4*)&h0[k0 + kq];
            }
        } else {
            while (ld_acq(fA) < (unsigned)t) { }
            const float* base = g_hs + ((size_t)(t - 1) * Bb + bbase) * Ee + k0 + kk;
            float4 v0 = __ldcg((const float4*)(base + (size_t)bq0 * Ee));
            float4 v1 = __ldcg((const float4*)(base + (size_t)bq1 * Ee));
            *(float4*)&myhsm[bq0 * 64 + kk] = v0;
            *(float4*)&myhsm[bq1 * 64 + kk] = v1;
        }
        __syncwarp();

        // ---- partial dots with 2-deep LDS pipeline ----
#pragma unroll
        for (int b = 0; b < 4; b++) {
            const ulonglong2* hp2 = (const ulonglong2*)(myhsm + b * 64);
            u64 aA0 = 0ull, aA1 = 0ull, aB0 = 0ull, aB1 = 0ull;
            ulonglong2 n0 = hp2[0], n1 = hp2[1];
#pragma unroll
            for (int j = 0; j < 8; j++) {
                ulonglong2 h2a = n0, h2b = n1;
                if (j < 7) { n0 = hp2[2 * j + 2]; n1 = hp2[2 * j + 3]; }
                aA0 = fma2(h2a.x, wA[4 * j + 0], aA0);
                aA1 = fma2(h2a.y, wA[4 * j + 1], aA1);
                aA0 = fma2(h2b.x, wA[4 * j + 2], aA0);
                aA1 = fma2(h2b.y, wA[4 * j + 3], aA1);
                aB0 = fma2(h2a.x, wB[4 * j + 0], aB0);
                aB1 = fma2(h2a.y, wB[4 * j + 1], aB1);
                aB0 = fma2(h2b.x, wB[4 * j + 2], aB0);
                aB1 = fma2(h2b.y, wB[4 * j + 3], aB1);
            }
            psum[p][ks * 288 + b * 72 + l]      = hsum(aA0) + hsum(aA1);
            psum[p][ks * 288 + b * 72 + l + 32] = hsum(aB0) + hsum(aB1);
        }
        __syncthreads();

        {
            float s = 0.f;
#pragma unroll
            for (int q = 0; q < 8; q++) s += psum[p][q * 288 + rb * 72 + rc];
            float val = tanhf(s + pv);
            g_hs[((size_t)t * Bb + bbase + rb) * Ee + obase + rc] = val;
            __syncwarp();
            if (l == 0 && t < Tt - 1) st_rel(myflag, (unsigned)(t + 1));
        }
    }
}

// ---------------- head GEMM: 128x64 block, 8x4 thread tile, k-major A ----------------
// out[b][t][v] = hs[t][b][:] · w_head[v][:] + b_head[v]
__global__ void __launch_bounds__(256)
head_gemm_kernel(const float* __restrict__ w_head,
                 const float* __restrict__ b_head,
                 float* __restrict__ out) {
    __shared__ __align__(16) float As2[16][128];   // 8 KB   [k][row]
    __shared__ __align__(16) float Bs[16][68];     // 4.25 KB [k][col] padded
    int tid = threadIdx.x;
    int rbase = blockIdx.x * 128;
    int cbase = blockIdx.y * 64;
    int ti = tid >> 4, tj = tid & 15;    // rows ti*8.., cols tj*4..
    int arow = tid >> 1, akq = (tid & 1) * 8;   // A fill: row, k-offset {0,8}
    int bcol = tid >> 2, bkq = (tid & 3) * 4;   // B fill

    float acc[8][4];
#pragma unroll
    for (int i = 0; i < 8; i++)
#pragma unroll
        for (int j = 0; j < 4; j++) acc[i][j] = 0.f;

    for (int k0 = 0; k0 < Ee; k0 += 16) {
        // A: 128 rows x 16 k, stored k-major (transposed)
#pragma unroll
        for (int h = 0; h < 2; h++) {
            float4 av = *(const float4*)&g_hs[(size_t)(rbase + arow) * Ee + k0 + akq + h * 4];
            As2[akq + h * 4 + 0][arow] = av.x;
            As2[akq + h * 4 + 1][arow] = av.y;
            As2[akq + h * 4 + 2][arow] = av.z;
            As2[akq + h * 4 + 3][arow] = av.w;
        }
        // B: 64 cols x 16 k, transposed store
        {
            float4 bv = *(const float4*)&w_head[(size_t)(cbase + bcol) * Ee + k0 + bkq];
            Bs[bkq + 0][bcol] = bv.x; Bs[bkq + 1][bcol] = bv.y;
            Bs[bkq + 2][bcol] = bv.z; Bs[bkq + 3][bcol] = bv.w;
        }
        __syncthreads();
#pragma unroll
        for (int kk = 0; kk < 16; kk++) {
            float4 aL = *(const float4*)&As2[kk][ti * 8];       // rows 0..3
            float4 aH = *(const float4*)&As2[kk][ti * 8 + 4];   // rows 4..7
            float4 b4 = *(const float4*)&Bs[kk][tj * 4];
            acc[0][0] = fmaf(aL.x, b4.x, acc[0][0]); acc[0][1] = fmaf(aL.x, b4.y, acc[0][1]);
            acc[0][2] = fmaf(aL.x, b4.z, acc[0][2]); acc[0][3] = fmaf(aL.x, b4.w, acc[0][3]);
            acc[1][0] = fmaf(aL.y, b4.x, acc[1][0]); acc[1][1] = fmaf(aL.y, b4.y, acc[1][1]);
            acc[1][2] = fmaf(aL.y, b4.z, acc[1][2]); acc[1][3] = fmaf(aL.y, b4.w, acc[1][3]);
            acc[2][0] = fmaf(aL.z, b4.x, acc[2][0]); acc[2][1] = fmaf(aL.z, b4.y, acc[2][1]);
            acc[2][2] = fmaf(aL.z, b4.z, acc[2][2]); acc[2][3] = fmaf(aL.z, b4.w, acc[2][3]);
            acc[3][0] = fmaf(aL.w, b4.x, acc[3][0]); acc[3][1] = fmaf(aL.w, b4.y, acc[3][1]);
            acc[3][2] = fmaf(aL.w, b4.z, acc[3][2]); acc[3][3] = fmaf(aL.w, b4.w, acc[3][3]);
            acc[4][0] = fmaf(aH.x, b4.x, acc[4][0]); acc[4][1] = fmaf(aH.x, b4.y, acc[4][1]);
            acc[4][2] = fmaf(aH.x, b4.z, acc[4][2]); acc[4][3] = fmaf(aH.x, b4.w, acc[4][3]);
            acc[5][0] = fmaf(aH.y, b4.x, acc[5][0]); acc[5][1] = fmaf(aH.y, b4.y, acc[5][1]);
            acc[5][2] = fmaf(aH.y, b4.z, acc[5][2]); acc[5][3] = fmaf(aH.y, b4.w, acc[5][3]);
            acc[6][0] = fmaf(aH.z, b4.x, acc[6][0]); acc[6][1] = fmaf(aH.z, b4.y, acc[6][1]);
            acc[6][2] = fmaf(aH.z, b4.z, acc[6][2]); acc[6][3] = fmaf(aH.z, b4.w, acc[6][3]);
            acc[7][0] = fmaf(aH.w, b4.x, acc[7][0]); acc[7][1] = fmaf(aH.w, b4.y, acc[7][1]);
            acc[7][2] = fmaf(aH.w, b4.z, acc[7][2]); acc[7][3] = fmaf(aH.w, b4.w, acc[7][3]);
        }
        __syncthreads();
    }
#pragma unroll
    for (int ii = 0; ii < 8; ii++) {
        int r  = rbase + ti * 8 + ii;      // r = t*B + b
        int bb = r & (Bb - 1);
        int tt = r >> 6;
        int cc = cbase + tj * 4;
        float4 o;
        o.x = acc[ii][0] + b_head[cc + 0];
        o.y = acc[ii][1] + b_head[cc + 1];
        o.z = acc[ii][2] + b_head[cc + 2];
        o.w = acc[ii][3] + b_head[cc + 3];
        *(float4*)&out[(size_t)bb * (Tt * Vv) + (size_t)tt * Vv + cc] = o;
    }
}

// ---------------- launch ----------------
extern "C" void kernel_launch(void* const* d_in, const int* in_sizes, int n_in,
                              void* d_out, int out_size) {
    const int*   x      = (const int*)  d_in[0];
    const float* emb    = (const float*)d_in[1];
    const float* w_cell = (const float*)d_in[2];
    const float* b_cell = (const float*)d_in[3];
    const float* w_head = (const float*)d_in[4];
    const float* b_head = (const float*)d_in[5];
    const float* h0     = (const float*)d_in[6];
    float* out = (float*)d_out;

    zero_flag_kernel<<<128, 256>>>();
    p_gemm_kernel<<<dim3(Vv / 64, Ee / 64), 256>>>(emb, w_cell, b_cell);
    rnn_rec_kernel<<<128, 256>>>(x, w_cell, h0);
    head_gemm_kernel<<<dim3((Bb * Tt) / 128, Vv / 64), 256>>>(w_head, b_head, out);
}